// round 3
// baseline (speedup 1.0000x reference)
#include <cuda_runtime.h>
#include <math.h>

#define HIDDEN 1024
#define BATCH  4
#define SEQ    2048
#define M_TOTAL (BATCH * SEQ)

// Scratch (device globals: allocation-free per harness rules)
__device__ float g_Q[(size_t)M_TOTAL * HIDDEN];
__device__ float g_K[(size_t)M_TOTAL * HIDDEN];
__device__ float g_V[(size_t)M_TOTAL * HIDDEN];
__device__ float g_P[(size_t)BATCH * SEQ * SEQ];

constexpr int BM = 64, BN = 64, BK = 16;
constexpr int SPAD = 68;  // padded row stride (floats): 16B-aligned, halves STS conflicts

// ---------------------------------------------------------------------------
// Kernel 1: fused QKV projection.  NT GEMM: C[m,n] = sum_k X[m,k]*W[n,k] + b[n]
// grid = (HIDDEN/BN, M_TOTAL/BM, 3), block = 256
// ---------------------------------------------------------------------------
__global__ void qkv_kernel(const float* __restrict__ x,
                           const float* __restrict__ Wq, const float* __restrict__ bq,
                           const float* __restrict__ Wk, const float* __restrict__ bk,
                           const float* __restrict__ Wv, const float* __restrict__ bv)
{
    __shared__ float As[BK][SPAD];
    __shared__ float Bs[BK][SPAD];

    const float* W; const float* bias; float* out;
    if (blockIdx.z == 0)      { W = Wq; bias = bq; out = g_Q; }
    else if (blockIdx.z == 1) { W = Wk; bias = bk; out = g_K; }
    else                      { W = Wv; bias = bv; out = g_V; }

    const int m0 = blockIdx.y * BM;
    const int n0 = blockIdx.x * BN;
    const int tid = threadIdx.x;
    const int tx = tid & 15, ty = tid >> 4;

    const int lrow = tid >> 2;         // 0..63
    const int lk4  = (tid & 3) << 2;   // 0,4,8,12

    float acc[4][4] = {};

    for (int k0 = 0; k0 < HIDDEN; k0 += BK) {
        float4 av = *reinterpret_cast<const float4*>(&x[(size_t)(m0 + lrow) * HIDDEN + k0 + lk4]);
        float4 bv4 = *reinterpret_cast<const float4*>(&W[(size_t)(n0 + lrow) * HIDDEN + k0 + lk4]);
        As[lk4 + 0][lrow] = av.x;  As[lk4 + 1][lrow] = av.y;
        As[lk4 + 2][lrow] = av.z;  As[lk4 + 3][lrow] = av.w;
        Bs[lk4 + 0][lrow] = bv4.x; Bs[lk4 + 1][lrow] = bv4.y;
        Bs[lk4 + 2][lrow] = bv4.z; Bs[lk4 + 3][lrow] = bv4.w;
        __syncthreads();
#pragma unroll
        for (int kk = 0; kk < BK; kk++) {
            float a[4], b[4];
            *reinterpret_cast<float4*>(a) = *reinterpret_cast<const float4*>(&As[kk][ty * 4]);
            *reinterpret_cast<float4*>(b) = *reinterpret_cast<const float4*>(&Bs[kk][tx * 4]);
#pragma unroll
            for (int i = 0; i < 4; i++)
#pragma unroll
                for (int j = 0; j < 4; j++)
                    acc[i][j] += a[i] * b[j];
        }
        __syncthreads();
    }

#pragma unroll
    for (int i = 0; i < 4; i++) {
        const int m = m0 + ty * 4 + i;
#pragma unroll
        for (int j = 0; j < 4; j++) {
            const int n = n0 + tx * 4 + j;
            out[(size_t)m * HIDDEN + n] = acc[i][j] + bias[n];
        }
    }
}

// ---------------------------------------------------------------------------
// Kernel 2: scores.  NT GEMM per batch: P[q,k] = (Q[q,:]·K[k,:]) * 1/32, masked
// grid = (SEQ/BN, SEQ/BM, BATCH), block = 256
// ---------------------------------------------------------------------------
__global__ void scores_kernel(const int* __restrict__ mask)
{
    __shared__ float As[BK][SPAD];
    __shared__ float Bs[BK][SPAD];

    const int b = blockIdx.z;
    const float* Qb = g_Q + (size_t)b * SEQ * HIDDEN;
    const float* Kb = g_K + (size_t)b * SEQ * HIDDEN;
    float* P        = g_P + (size_t)b * SEQ * SEQ;
    const int* mb   = mask + (size_t)b * SEQ * SEQ;

    const int m0 = blockIdx.y * BM;
    const int n0 = blockIdx.x * BN;
    const int tid = threadIdx.x;
    const int tx = tid & 15, ty = tid >> 4;
    const int lrow = tid >> 2;
    const int lk4  = (tid & 3) << 2;

    float acc[4][4] = {};

    for (int k0 = 0; k0 < HIDDEN; k0 += BK) {
        float4 av = *reinterpret_cast<const float4*>(&Qb[(size_t)(m0 + lrow) * HIDDEN + k0 + lk4]);
        float4 bv4 = *reinterpret_cast<const float4*>(&Kb[(size_t)(n0 + lrow) * HIDDEN + k0 + lk4]);
        As[lk4 + 0][lrow] = av.x;  As[lk4 + 1][lrow] = av.y;
        As[lk4 + 2][lrow] = av.z;  As[lk4 + 3][lrow] = av.w;
        Bs[lk4 + 0][lrow] = bv4.x; Bs[lk4 + 1][lrow] = bv4.y;
        Bs[lk4 + 2][lrow] = bv4.z; Bs[lk4 + 3][lrow] = bv4.w;
        __syncthreads();
#pragma unroll
        for (int kk = 0; kk < BK; kk++) {
            float a[4], b4[4];
            *reinterpret_cast<float4*>(a)  = *reinterpret_cast<const float4*>(&As[kk][ty * 4]);
            *reinterpret_cast<float4*>(b4) = *reinterpret_cast<const float4*>(&Bs[kk][tx * 4]);
#pragma unroll
            for (int i = 0; i < 4; i++)
#pragma unroll
                for (int j = 0; j < 4; j++)
                    acc[i][j] += a[i] * b4[j];
        }
        __syncthreads();
    }

    const float scale = 0.03125f;  // 1/sqrt(1024)
#pragma unroll
    for (int i = 0; i < 4; i++) {
        const int q = m0 + ty * 4 + i;
#pragma unroll
        for (int j = 0; j < 4; j++) {
            const int kc = n0 + tx * 4 + j;
            const int mv = mb[(size_t)q * SEQ + kc];
            P[(size_t)q * SEQ + kc] = mv ? acc[i][j] * scale : -INFINITY;
        }
    }
}

// ---------------------------------------------------------------------------
// Kernel 3: row softmax over g_P.  grid = BATCH*SEQ blocks of 256 threads.
// ---------------------------------------------------------------------------
__global__ void softmax_kernel()
{
    float* P = g_P + (size_t)blockIdx.x * SEQ;
    const int tid = threadIdx.x;

    float v[8];
    float m = -INFINITY;
#pragma unroll
    for (int i = 0; i < 8; i++) {
        v[i] = P[i * 256 + tid];
        m = fmaxf(m, v[i]);
    }
#pragma unroll
    for (int o = 16; o > 0; o >>= 1) m = fmaxf(m, __shfl_xor_sync(0xffffffffu, m, o));
    __shared__ float smax[8];
    if ((tid & 31) == 0) smax[tid >> 5] = m;
    __syncthreads();
    float mm = smax[0];
#pragma unroll
    for (int i = 1; i < 8; i++) mm = fmaxf(mm, smax[i]);

    float s = 0.f;
#pragma unroll
    for (int i = 0; i < 8; i++) { v[i] = __expf(v[i] - mm); s += v[i]; }
#pragma unroll
    for (int o = 16; o > 0; o >>= 1) s += __shfl_xor_sync(0xffffffffu, s, o);
    __shared__ float ssum[8];
    if ((tid & 31) == 0) ssum[tid >> 5] = s;
    __syncthreads();
    float tot = 0.f;
#pragma unroll
    for (int i = 0; i < 8; i++) tot += ssum[i];
    const float inv = 1.0f / tot;
#pragma unroll
    for (int i = 0; i < 8; i++) P[i * 256 + tid] = v[i] * inv;
}

// ---------------------------------------------------------------------------
// Kernel 4: out = P @ V.  NN GEMM per batch: O[q,h] = sum_k P[q,k]*V[k,h]
// grid = (HIDDEN/BN, SEQ/BM, BATCH), block = 256
// ---------------------------------------------------------------------------
__global__ void av_kernel(float* __restrict__ out)
{
    __shared__ float As[BK][SPAD];
    __shared__ float Bs[BK][SPAD];

    const int b = blockIdx.z;
    const float* A  = g_P + (size_t)b * SEQ * SEQ;
    const float* Bv = g_V + (size_t)b * SEQ * HIDDEN;
    float* O        = out + (size_t)b * SEQ * HIDDEN;

    const int m0 = blockIdx.y * BM;
    const int n0 = blockIdx.x * BN;
    const int tid = threadIdx.x;
    const int tx = tid & 15, ty = tid >> 4;

    const int lrow = tid >> 2;          // A tile: 0..63
    const int lk4  = (tid & 3) << 2;
    const int brow = tid >> 4;          // B tile: 0..15
    const int bn4  = (tid & 15) << 2;

    float acc[4][4] = {};

    for (int k0 = 0; k0 < SEQ; k0 += BK) {
        float4 av = *reinterpret_cast<const float4*>(&A[(size_t)(m0 + lrow) * SEQ + k0 + lk4]);
        As[lk4 + 0][lrow] = av.x; As[lk4 + 1][lrow] = av.y;
        As[lk4 + 2][lrow] = av.z; As[lk4 + 3][lrow] = av.w;
        *reinterpret_cast<float4*>(&Bs[brow][bn4]) =
            *reinterpret_cast<const float4*>(&Bv[(size_t)(k0 + brow) * HIDDEN + n0 + bn4]);
        __syncthreads();
#pragma unroll
        for (int kk = 0; kk < BK; kk++) {
            float a[4], b4[4];
            *reinterpret_cast<float4*>(a)  = *reinterpret_cast<const float4*>(&As[kk][ty * 4]);
            *reinterpret_cast<float4*>(b4) = *reinterpret_cast<const float4*>(&Bs[kk][tx * 4]);
#pragma unroll
            for (int i = 0; i < 4; i++)
#pragma unroll
                for (int j = 0; j < 4; j++)
                    acc[i][j] += a[i] * b4[j];
        }
        __syncthreads();
    }

#pragma unroll
    for (int i = 0; i < 4; i++) {
        const int m = m0 + ty * 4 + i;
#pragma unroll
        for (int j = 0; j < 4; j++) {
            const int n = n0 + tx * 4 + j;
            O[(size_t)m * HIDDEN + n] = acc[i][j];
        }
    }
}

// ---------------------------------------------------------------------------
extern "C" void kernel_launch(void* const* d_in, const int* in_sizes, int n_in,
                              void* d_out, int out_size)
{
    const float* x   = (const float*)d_in[0];
    const int*  mask = (const int*)  d_in[1];
    const float* Wq  = (const float*)d_in[2];
    const float* bq  = (const float*)d_in[3];
    const float* Wk  = (const float*)d_in[4];
    const float* bk  = (const float*)d_in[5];
    const float* Wv  = (const float*)d_in[6];
    const float* bv  = (const float*)d_in[7];
    float* out = (float*)d_out;

    dim3 blk(256);
    qkv_kernel<<<dim3(HIDDEN / BN, M_TOTAL / BM, 3), blk>>>(x, Wq, bq, Wk, bk, Wv, bv);
    scores_kernel<<<dim3(SEQ / BN, SEQ / BM, BATCH), blk>>>(mask);
    softmax_kernel<<<dim3(BATCH * SEQ), blk>>>();
    av_kernel<<<dim3(HIDDEN / BN, SEQ / BM, BATCH), blk>>>(out);
}

// round 8
// speedup vs baseline: 1.6515x; 1.6515x over previous
#include <cuda_runtime.h>
#include <cuda_bf16.h>
#include <cstdint>
#include <math.h>

#define H       1024
#define BATCH   4
#define SEQ     2048
#define M_ALL   (BATCH * SEQ)

// ---------------------------------------------------------------------------
// Tiling: CTA 128x128, K-chunk 32, 8 warps (2 rows x 4 cols), warp tile 64x32
// ---------------------------------------------------------------------------
constexpr int RB          = 80;                // smem bytes/row (64B data + 16B pad)
constexpr int TILE_BYTES  = 128 * RB;          // 10240
constexpr int STAGE_BYTES = 4 * TILE_BYTES;    // Ah, Al, Bh, Bl
constexpr int SMEM_BYTES  = 2 * STAGE_BYTES;   // 81920 (double buffered)
constexpr int SF          = 132;               // epilogue f32 row stride

// ---------------------------------------------------------------------------
// PTX helpers (sm_103 baseline ISA only: ldmatrix / mma.sync / cp.async)
// ---------------------------------------------------------------------------
__device__ __forceinline__ uint32_t smem_to_u32(const void* p) {
    uint32_t a;
    asm("{ .reg .u64 t; cvta.to.shared.u64 t, %1; cvt.u32.u64 %0, t; }" : "=r"(a) : "l"(p));
    return a;
}

#define CP_ASYNC16(dst, src) \
    asm volatile("cp.async.cg.shared.global [%0], [%1], 16;" :: "r"(dst), "l"(src))
#define CP_COMMIT() asm volatile("cp.async.commit_group;" ::: "memory")
#define CP_WAIT(n)  asm volatile("cp.async.wait_group %0;" :: "n"(n) : "memory")

#define LDSM_X4(r0, r1, r2, r3, addr) \
    asm volatile("ldmatrix.sync.aligned.m8n8.x4.shared.b16 {%0,%1,%2,%3}, [%4];" \
        : "=r"(r0), "=r"(r1), "=r"(r2), "=r"(r3) : "r"(addr))

__device__ __forceinline__ void mma16816(float* c, const uint32_t* a,
                                         uint32_t b0, uint32_t b1) {
    asm volatile(
        "mma.sync.aligned.m16n8k16.row.col.f32.bf16.bf16.f32 "
        "{%0,%1,%2,%3}, {%4,%5,%6,%7}, {%8,%9}, {%0,%1,%2,%3};"
        : "+f"(c[0]), "+f"(c[1]), "+f"(c[2]), "+f"(c[3])
        : "r"(a[0]), "r"(a[1]), "r"(a[2]), "r"(a[3]), "r"(b0), "r"(b1));
}

// ---------------------------------------------------------------------------
// Scratch (device globals; allocation-free)
// ---------------------------------------------------------------------------
__device__ __align__(256) __nv_bfloat16 g_Xh[(size_t)M_ALL * H];
__device__ __align__(256) __nv_bfloat16 g_Xl[(size_t)M_ALL * H];
__device__ __align__(256) __nv_bfloat16 g_Wh[3 * (size_t)H * H];
__device__ __align__(256) __nv_bfloat16 g_Wl[3 * (size_t)H * H];
__device__ __align__(256) __nv_bfloat16 g_Qh[(size_t)M_ALL * H];
__device__ __align__(256) __nv_bfloat16 g_Ql[(size_t)M_ALL * H];
__device__ __align__(256) __nv_bfloat16 g_Kh[(size_t)M_ALL * H];
__device__ __align__(256) __nv_bfloat16 g_Kl[(size_t)M_ALL * H];
__device__ __align__(256) __nv_bfloat16 g_Vth[(size_t)BATCH * H * SEQ];  // [b][h][s]
__device__ __align__(256) __nv_bfloat16 g_Vtl[(size_t)BATCH * H * SEQ];
__device__ __align__(256) float         g_S [(size_t)BATCH * SEQ * SEQ];
__device__ __align__(256) __nv_bfloat16 g_Ph[(size_t)BATCH * SEQ * SEQ];
__device__ __align__(256) __nv_bfloat16 g_Pl[(size_t)BATCH * SEQ * SEQ];

// ---------------------------------------------------------------------------
// Stage one 128x32 bf16 tile (K-contiguous rows) into padded smem via cp.async
// ---------------------------------------------------------------------------
__device__ __forceinline__ void stage_in(const __nv_bfloat16* __restrict__ g,
                                         size_t ld, int k0, uint32_t dst, int tid) {
#pragma unroll
    for (int i = 0; i < 2; i++) {
        int u = i * 256 + tid;      // 0..511
        int row = u >> 2, c = u & 3;
        const __nv_bfloat16* src = g + (size_t)row * ld + k0 + c * 8;
        CP_ASYNC16(dst + row * RB + c * 16, src);
    }
}

__device__ __forceinline__ void stage_all(const __nv_bfloat16* Ah, const __nv_bfloat16* Al,
                                          size_t lda,
                                          const __nv_bfloat16* Bh, const __nv_bfloat16* Bl,
                                          size_t ldb, int k0, uint32_t sb, int tid) {
    stage_in(Ah, lda, k0, sb + 0 * TILE_BYTES, tid);
    stage_in(Al, lda, k0, sb + 1 * TILE_BYTES, tid);
    stage_in(Bh, ldb, k0, sb + 2 * TILE_BYTES, tid);
    stage_in(Bl, ldb, k0, sb + 3 * TILE_BYTES, tid);
    CP_COMMIT();
}

// ---------------------------------------------------------------------------
// Compute one 32-wide K-chunk from a resident stage: 2 k16 steps x 3 products
// ---------------------------------------------------------------------------
__device__ __forceinline__ void compute_stage(uint32_t st_base, uint32_t aByte,
                                              uint32_t bByte, float (&acc)[4][4][4]) {
#pragma unroll
    for (int ks = 0; ks < 2; ks++) {
        uint32_t ah[4][4], al[4][4], bh[2][4], bl[2][4];
#pragma unroll
        for (int mt = 0; mt < 4; mt++) {
            uint32_t ao = st_base + aByte + mt * 16 * RB + ks * 32;
            LDSM_X4(ah[mt][0], ah[mt][1], ah[mt][2], ah[mt][3], ao + 0 * TILE_BYTES);
            LDSM_X4(al[mt][0], al[mt][1], al[mt][2], al[mt][3], ao + 1 * TILE_BYTES);
        }
#pragma unroll
        for (int np = 0; np < 2; np++) {
            uint32_t bo = st_base + bByte + np * 16 * RB + ks * 32;
            LDSM_X4(bh[np][0], bh[np][1], bh[np][2], bh[np][3], bo + 2 * TILE_BYTES);
            LDSM_X4(bl[np][0], bl[np][1], bl[np][2], bl[np][3], bo + 3 * TILE_BYTES);
        }
#pragma unroll
        for (int mt = 0; mt < 4; mt++)
#pragma unroll
            for (int nt = 0; nt < 4; nt++) {
                const uint32_t b0h = bh[nt >> 1][(nt & 1) * 2];
                const uint32_t b1h = bh[nt >> 1][(nt & 1) * 2 + 1];
                const uint32_t b0l = bl[nt >> 1][(nt & 1) * 2];
                const uint32_t b1l = bl[nt >> 1][(nt & 1) * 2 + 1];
                mma16816(acc[mt][nt], ah[mt], b0h, b1h);
                mma16816(acc[mt][nt], ah[mt], b0l, b1l);
                mma16816(acc[mt][nt], al[mt], b0h, b1h);
            }
    }
}

// ---------------------------------------------------------------------------
// Full mainloop: D(128x128 f32, in registers) = AhBh + AhBl + AlBh over Kdim
// ---------------------------------------------------------------------------
__device__ __forceinline__ void gemm_core(const __nv_bfloat16* Ah, const __nv_bfloat16* Al,
                                          size_t lda,
                                          const __nv_bfloat16* Bh, const __nv_bfloat16* Bl,
                                          size_t ldb, int Kdim, uint32_t sbase, int tid,
                                          float (&acc)[4][4][4]) {
    const int lane = tid & 31, wid = tid >> 5;
    const int wr = wid >> 2, wc = wid & 3;
    // ldmatrix per-lane base offsets (A: m = lane%16, kblk = lane/16;
    //                                 B: n = lane%8 + 8*((lane/16)&1), kblk = (lane/8)&1)
    const uint32_t aByte = sbase + (uint32_t)((wr * 64 + (lane & 15)) * RB + (lane >> 4) * 16);
    const uint32_t bByte = sbase + (uint32_t)((wc * 32 + (lane & 7) + ((lane >> 4) & 1) * 8) * RB
                                              + ((lane >> 3) & 1) * 16);

    const int nch = Kdim / 32;
    stage_all(Ah, Al, lda, Bh, Bl, ldb, 0, sbase, tid);
#pragma unroll 1
    for (int c = 0; c < nch - 1; c++) {
        stage_all(Ah, Al, lda, Bh, Bl, ldb, (c + 1) * 32,
                  sbase + (uint32_t)(((c + 1) & 1) * STAGE_BYTES), tid);
        CP_WAIT(1);
        __syncthreads();
        compute_stage((uint32_t)((c & 1) * STAGE_BYTES), aByte, bByte, acc);
        __syncthreads();
    }
    CP_WAIT(0);
    __syncthreads();
    compute_stage((uint32_t)(((nch - 1) & 1) * STAGE_BYTES), aByte, bByte, acc);
    __syncthreads();
}

// Scatter warp accumulators into a 128x128 f32 smem tile (stride SF)
__device__ __forceinline__ void acc_to_smem(float (&acc)[4][4][4], float* smf, int tid) {
    const int lane = tid & 31, wid = tid >> 5;
    const int wr = wid >> 2, wc = wid & 3;
    const int g = lane >> 2, t = lane & 3;
#pragma unroll
    for (int mt = 0; mt < 4; mt++)
#pragma unroll
        for (int nt = 0; nt < 4; nt++) {
            const int m = wr * 64 + mt * 16 + g;
            const int n = wc * 32 + nt * 8 + 2 * t;
            *reinterpret_cast<float2*>(&smf[m * SF + n]) =
                make_float2(acc[mt][nt][0], acc[mt][nt][1]);
            *reinterpret_cast<float2*>(&smf[(m + 8) * SF + n]) =
                make_float2(acc[mt][nt][2], acc[mt][nt][3]);
        }
}

// ---------------------------------------------------------------------------
// Kernel: fp32 -> (hi, lo) bf16 split
// ---------------------------------------------------------------------------
__global__ void split_kernel(const float* __restrict__ src,
                             __nv_bfloat16* __restrict__ dh,
                             __nv_bfloat16* __restrict__ dl, int n4) {
    int i = blockIdx.x * blockDim.x + threadIdx.x;
    if (i >= n4) return;
    float4 v = reinterpret_cast<const float4*>(src)[i];
    float vv[4] = {v.x, v.y, v.z, v.w};
    __nv_bfloat16 hh[4], ll[4];
#pragma unroll
    for (int j = 0; j < 4; j++) {
        hh[j] = __float2bfloat16(vv[j]);
        ll[j] = __float2bfloat16(vv[j] - __bfloat162float(hh[j]));
    }
    reinterpret_cast<__nv_bfloat162*>(dh)[2 * i]     = __halves2bfloat162(hh[0], hh[1]);
    reinterpret_cast<__nv_bfloat162*>(dh)[2 * i + 1] = __halves2bfloat162(hh[2], hh[3]);
    reinterpret_cast<__nv_bfloat162*>(dl)[2 * i]     = __halves2bfloat162(ll[0], ll[1]);
    reinterpret_cast<__nv_bfloat162*>(dl)[2 * i + 1] = __halves2bfloat162(ll[2], ll[3]);
}

// ---------------------------------------------------------------------------
// Kernel 1: QKV projection.  z=0 -> Q (split), z=1 -> K (split), z=2 -> V^T
// grid = (H/128, M_ALL/128, 3), block = 256
// ---------------------------------------------------------------------------
__global__ void __launch_bounds__(256, 1)
qkv_kernel(const float* __restrict__ bq, const float* __restrict__ bk,
           const float* __restrict__ bv) {
    extern __shared__ char sm[];
    const uint32_t sbase = smem_to_u32(sm);
    const int tid = threadIdx.x;
    const int z = blockIdx.z;
    const int m0 = blockIdx.y * 128, n0 = blockIdx.x * 128;

    const __nv_bfloat16* Ah = g_Xh + (size_t)m0 * H;
    const __nv_bfloat16* Al = g_Xl + (size_t)m0 * H;
    const __nv_bfloat16* Bh = g_Wh + (size_t)z * H * H + (size_t)n0 * H;
    const __nv_bfloat16* Bl = g_Wl + (size_t)z * H * H + (size_t)n0 * H;
    const float* bias = (z == 0) ? bq : (z == 1) ? bk : bv;

    float acc[4][4][4] = {};
    gemm_core(Ah, Al, H, Bh, Bl, H, H, sbase, tid, acc);

    float* smf = reinterpret_cast<float*>(sm);
    acc_to_smem(acc, smf, tid);
    __syncthreads();

    if (z < 2) {
        __nv_bfloat16* outH = (z == 0) ? g_Qh : g_Kh;
        __nv_bfloat16* outL = (z == 0) ? g_Ql : g_Kl;
        const int row = tid >> 1, ch = (tid & 1) * 64;
        uint32_t ph[32], pl[32];
#pragma unroll
        for (int j = 0; j < 32; j++) {
            float c0 = smf[row * SF + ch + 2 * j]     + bias[n0 + ch + 2 * j];
            float c1 = smf[row * SF + ch + 2 * j + 1] + bias[n0 + ch + 2 * j + 1];
            __nv_bfloat16 h0 = __float2bfloat16(c0), h1 = __float2bfloat16(c1);
            __nv_bfloat16 l0 = __float2bfloat16(c0 - __bfloat162float(h0));
            __nv_bfloat16 l1 = __float2bfloat16(c1 - __bfloat162float(h1));
            __nv_bfloat162 vh = __halves2bfloat162(h0, h1);
            __nv_bfloat162 vl = __halves2bfloat162(l0, l1);
            ph[j] = *reinterpret_cast<uint32_t*>(&vh);
            pl[j] = *reinterpret_cast<uint32_t*>(&vl);
        }
        const size_t go = (size_t)(m0 + row) * H + n0 + ch;
        uint4* dh = reinterpret_cast<uint4*>(outH + go);
        uint4* dl = reinterpret_cast<uint4*>(outL + go);
#pragma unroll
        for (int q = 0; q < 8; q++) {
            dh[q] = reinterpret_cast<const uint4*>(ph)[q];
            dl[q] = reinterpret_cast<const uint4*>(pl)[q];
        }
    } else {
        // V transposed: Vt[b][n][s]; threads map to s -> coalesced stores
        const int b = m0 >> 11;
        const int s0 = m0 & 2047;
        const int sl = tid & 127, nh = (tid >> 7) * 64;
#pragma unroll 1
        for (int j = 0; j < 64; j++) {
            const int nl = nh + j;
            float c = smf[sl * SF + nl] + bias[n0 + nl];
            __nv_bfloat16 hv = __float2bfloat16(c);
            __nv_bfloat16 lv = __float2bfloat16(c - __bfloat162float(hv));
            const size_t a = (size_t)b * H * SEQ + (size_t)(n0 + nl) * SEQ + s0 + sl;
            g_Vth[a] = hv;
            g_Vtl[a] = lv;
        }
    }
}

// ---------------------------------------------------------------------------
// Kernel 2: scores S = mask ? (Q.K^T)/32 : -inf.  grid = (16, 16, 4), block 256
// ---------------------------------------------------------------------------
__global__ void __launch_bounds__(256, 1)
scores_kernel(const int* __restrict__ mask) {
    extern __shared__ char sm[];
    const uint32_t sbase = smem_to_u32(sm);
    const int tid = threadIdx.x;
    const int b = blockIdx.z;
    const int m0 = blockIdx.y * 128, n0 = blockIdx.x * 128;

    const size_t rowA = (size_t)(b * SEQ + m0) * H;
    const size_t rowB = (size_t)(b * SEQ + n0) * H;

    float acc[4][4][4] = {};
    gemm_core(g_Qh + rowA, g_Ql + rowA, H, g_Kh + rowB, g_Kl + rowB, H, H,
              sbase, tid, acc);

    float* smf = reinterpret_cast<float*>(sm);
    acc_to_smem(acc, smf, tid);
    __syncthreads();

    const float scale = 0.03125f;  // 1/sqrt(1024)
    const int ql = tid >> 1, ch = (tid & 1) * 64;
    const size_t base = ((size_t)(b * SEQ + m0 + ql)) * SEQ + n0 + ch;
    const int4* mk4 = reinterpret_cast<const int4*>(mask + base);
    float4* dst = reinterpret_cast<float4*>(g_S + base);
#pragma unroll
    for (int j4 = 0; j4 < 16; j4++) {
        float4 v = *reinterpret_cast<const float4*>(&smf[ql * SF + ch + j4 * 4]);
        int4 mk = mk4[j4];
        v.x = mk.x ? v.x * scale : -INFINITY;
        v.y = mk.y ? v.y * scale : -INFINITY;
        v.z = mk.z ? v.z * scale : -INFINITY;
        v.w = mk.w ? v.w * scale : -INFINITY;
        dst[j4] = v;
    }
}

// ---------------------------------------------------------------------------
// Kernel 3: row softmax, fp32 in -> split-bf16 P out.  grid = B*S, block 256
// ---------------------------------------------------------------------------
__global__ void softmax_kernel() {
    const size_t row = (size_t)blockIdx.x * SEQ;
    const float* Srow = g_S + row;
    const int tid = threadIdx.x;

    float v[8];
    float m = -INFINITY;
#pragma unroll
    for (int i = 0; i < 8; i++) {
        v[i] = Srow[i * 256 + tid];
        m = fmaxf(m, v[i]);
    }
#pragma unroll
    for (int o = 16; o > 0; o >>= 1) m = fmaxf(m, __shfl_xor_sync(0xffffffffu, m, o));
    __shared__ float smax[8];
    if ((tid & 31) == 0) smax[tid >> 5] = m;
    __syncthreads();
    float mm = smax[0];
#pragma unroll
    for (int i = 1; i < 8; i++) mm = fmaxf(mm, smax[i]);

    float s = 0.f;
#pragma unroll
    for (int i = 0; i < 8; i++) { v[i] = __expf(v[i] - mm); s += v[i]; }
#pragma unroll
    for (int o = 16; o > 0; o >>= 1) s += __shfl_xor_sync(0xffffffffu, s, o);
    __shared__ float ssum[8];
    if ((tid & 31) == 0) ssum[tid >> 5] = s;
    __syncthreads();
    float tot = 0.f;
#pragma unroll
    for (int i = 0; i < 8; i++) tot += ssum[i];
    const float inv = 1.0f / tot;
#pragma unroll
    for (int i = 0; i < 8; i++) {
        float p = v[i] * inv;
        __nv_bfloat16 h = __float2bfloat16(p);
        __nv_bfloat16 l = __float2bfloat16(p - __bfloat162float(h));
        g_Ph[row + i * 256 + tid] = h;
        g_Pl[row + i * 256 + tid] = l;
    }
}

// ---------------------------------------------------------------------------
// Kernel 4: out = P @ V (NT vs V^T).  grid = (H/128, SEQ/128, 4), block 256
// ---------------------------------------------------------------------------
__global__ void __launch_bounds__(256, 1)
pv_kernel(float* __restrict__ out) {
    extern __shared__ char sm[];
    const uint32_t sbase = smem_to_u32(sm);
    const int tid = threadIdx.x;
    const int b = blockIdx.z;
    const int m0 = blockIdx.y * 128, n0 = blockIdx.x * 128;

    const size_t rowA = ((size_t)b * SEQ + m0) * SEQ;
    const size_t rowB = (size_t)b * H * SEQ + (size_t)n0 * SEQ;

    float acc[4][4][4] = {};
    gemm_core(g_Ph + rowA, g_Pl + rowA, SEQ, g_Vth + rowB, g_Vtl + rowB, SEQ, SEQ,
              sbase, tid, acc);

    float* smf = reinterpret_cast<float*>(sm);
    acc_to_smem(acc, smf, tid);
    __syncthreads();

    const int row = tid >> 1, ch = (tid & 1) * 64;
    const size_t base = ((size_t)(b * SEQ + m0 + row)) * H + n0 + ch;
    float4* dst = reinterpret_cast<float4*>(out + base);
#pragma unroll
    for (int j4 = 0; j4 < 16; j4++)
        dst[j4] = *reinterpret_cast<const float4*>(&smf[row * SF + ch + j4 * 4]);
}

// ---------------------------------------------------------------------------
extern "C" void kernel_launch(void* const* d_in, const int* in_sizes, int n_in,
                              void* d_out, int out_size) {
    const float* x   = (const float*)d_in[0];
    const int*  mask = (const int*)  d_in[1];
    const float* Wq  = (const float*)d_in[2];
    const float* bq  = (const float*)d_in[3];
    const float* Wk  = (const float*)d_in[4];
    const float* bk  = (const float*)d_in[5];
    const float* Wv  = (const float*)d_in[6];
    const float* bv  = (const float*)d_in[7];
    float* out = (float*)d_out;

    cudaFuncSetAttribute(qkv_kernel,    cudaFuncAttributeMaxDynamicSharedMemorySize, SMEM_BYTES);
    cudaFuncSetAttribute(scores_kernel, cudaFuncAttributeMaxDynamicSharedMemorySize, SMEM_BYTES);
    cudaFuncSetAttribute(pv_kernel,     cudaFuncAttributeMaxDynamicSharedMemorySize, SMEM_BYTES);

    __nv_bfloat16 *Xh, *Xl, *Wh, *Wl;
    cudaGetSymbolAddress((void**)&Xh, g_Xh);
    cudaGetSymbolAddress((void**)&Xl, g_Xl);
    cudaGetSymbolAddress((void**)&Wh, g_Wh);
    cudaGetSymbolAddress((void**)&Wl, g_Wl);

    const int n4x = M_ALL * H / 4;
    const int n4w = H * H / 4;
    split_kernel<<<n4x / 256, 256>>>(x, Xh, Xl, n4x);
    split_kernel<<<n4w / 256, 256>>>(Wq, Wh + 0 * (size_t)H * H, Wl + 0 * (size_t)H * H, n4w);
    split_kernel<<<n4w / 256, 256>>>(Wk, Wh + 1 * (size_t)H * H, Wl + 1 * (size_t)H * H, n4w);
    split_kernel<<<n4w / 256, 256>>>(Wv, Wh + 2 * (size_t)H * H, Wl + 2 * (size_t)H * H, n4w);

    qkv_kernel   <<<dim3(H / 128, M_ALL / 128, 3), 256, SMEM_BYTES>>>(bq, bk, bv);
    scores_kernel<<<dim3(SEQ / 128, SEQ / 128, BATCH), 256, SMEM_BYTES>>>(mask);
    softmax_kernel<<<BATCH * SEQ, 256>>>();
    pv_kernel    <<<dim3(H / 128, SEQ / 128, BATCH), 256, SMEM_BYTES>>>(out);
}

// round 10
// speedup vs baseline: 2.5806x; 1.5626x over previous
#include <cuda_runtime.h>
#include <cuda_bf16.h>
#include <cstdint>
#include <math.h>

#define H       1024
#define BATCH   4
#define SEQ     2048
#define M_ALL   (BATCH * SEQ)

// ---------------------------------------------------------------------------
// Tiling: CTA 128x128, K-chunk 32, 8 warps (2 rows x 4 cols), warp tile 64x32
// 3-stage cp.async pipeline, one __syncthreads per chunk.
// ---------------------------------------------------------------------------
constexpr int RB          = 80;                // smem bytes/row (64B data + 16B pad)
constexpr int TILE_BYTES  = 128 * RB;          // 10240
constexpr int STAGE_BYTES = 4 * TILE_BYTES;    // Ah, Al, Bh, Bl
constexpr int NSTAGE      = 3;
constexpr int SMEM_BYTES  = NSTAGE * STAGE_BYTES;  // 122880
constexpr int SF          = 132;               // epilogue f32 row stride

// ---------------------------------------------------------------------------
// PTX helpers (sm_103 baseline ISA only: ldmatrix / mma.sync / cp.async)
// ---------------------------------------------------------------------------
__device__ __forceinline__ uint32_t smem_to_u32(const void* p) {
    uint32_t a;
    asm("{ .reg .u64 t; cvta.to.shared.u64 t, %1; cvt.u32.u64 %0, t; }" : "=r"(a) : "l"(p));
    return a;
}

#define CP_ASYNC16(dst, src) \
    asm volatile("cp.async.cg.shared.global [%0], [%1], 16;" :: "r"(dst), "l"(src))
#define CP_COMMIT() asm volatile("cp.async.commit_group;" ::: "memory")
#define CP_WAIT(n)  asm volatile("cp.async.wait_group %0;" :: "n"(n) : "memory")

#define LDSM_X4(r0, r1, r2, r3, addr) \
    asm volatile("ldmatrix.sync.aligned.m8n8.x4.shared.b16 {%0,%1,%2,%3}, [%4];" \
        : "=r"(r0), "=r"(r1), "=r"(r2), "=r"(r3) : "r"(addr))

__device__ __forceinline__ void mma16816(float* c, const uint32_t* a,
                                         uint32_t b0, uint32_t b1) {
    asm volatile(
        "mma.sync.aligned.m16n8k16.row.col.f32.bf16.bf16.f32 "
        "{%0,%1,%2,%3}, {%4,%5,%6,%7}, {%8,%9}, {%0,%1,%2,%3};"
        : "+f"(c[0]), "+f"(c[1]), "+f"(c[2]), "+f"(c[3])
        : "r"(a[0]), "r"(a[1]), "r"(a[2]), "r"(a[3]), "r"(b0), "r"(b1));
}

// ---------------------------------------------------------------------------
// Scratch (device globals; allocation-free)
// ---------------------------------------------------------------------------
__device__ __align__(256) __nv_bfloat16 g_Xh[(size_t)M_ALL * H];
__device__ __align__(256) __nv_bfloat16 g_Xl[(size_t)M_ALL * H];
__device__ __align__(256) __nv_bfloat16 g_Wh[3 * (size_t)H * H];
__device__ __align__(256) __nv_bfloat16 g_Wl[3 * (size_t)H * H];
__device__ __align__(256) __nv_bfloat16 g_Qh[(size_t)M_ALL * H];
__device__ __align__(256) __nv_bfloat16 g_Ql[(size_t)M_ALL * H];
__device__ __align__(256) __nv_bfloat16 g_Kh[(size_t)M_ALL * H];
__device__ __align__(256) __nv_bfloat16 g_Kl[(size_t)M_ALL * H];
__device__ __align__(256) __nv_bfloat16 g_Vth[(size_t)BATCH * H * SEQ];  // [b][h][s]
__device__ __align__(256) __nv_bfloat16 g_Vtl[(size_t)BATCH * H * SEQ];
__device__ __align__(256) float         g_S [(size_t)BATCH * SEQ * SEQ];
__device__ __align__(256) __nv_bfloat16 g_Ph[(size_t)BATCH * SEQ * SEQ];
__device__ __align__(256) __nv_bfloat16 g_Pl[(size_t)BATCH * SEQ * SEQ];

// ---------------------------------------------------------------------------
// Stage one 128x32 bf16 tile (K-contiguous rows) into padded smem via cp.async
// ---------------------------------------------------------------------------
__device__ __forceinline__ void stage_in(const __nv_bfloat16* __restrict__ g,
                                         size_t ld, int k0, uint32_t dst, int tid) {
#pragma unroll
    for (int i = 0; i < 2; i++) {
        int u = i * 256 + tid;      // 0..511
        int row = u >> 2, c = u & 3;
        const __nv_bfloat16* src = g + (size_t)row * ld + k0 + c * 8;
        CP_ASYNC16(dst + row * RB + c * 16, src);
    }
}

__device__ __forceinline__ void stage_all(const __nv_bfloat16* Ah, const __nv_bfloat16* Al,
                                          size_t lda,
                                          const __nv_bfloat16* Bh, const __nv_bfloat16* Bl,
                                          size_t ldb, int k0, uint32_t sb, int tid) {
    stage_in(Ah, lda, k0, sb + 0 * TILE_BYTES, tid);
    stage_in(Al, lda, k0, sb + 1 * TILE_BYTES, tid);
    stage_in(Bh, ldb, k0, sb + 2 * TILE_BYTES, tid);
    stage_in(Bl, ldb, k0, sb + 3 * TILE_BYTES, tid);
    CP_COMMIT();
}

// ---------------------------------------------------------------------------
// Compute one 32-wide K-chunk from a resident stage: 2 k16 steps x 3 products
// ---------------------------------------------------------------------------
__device__ __forceinline__ void compute_stage(uint32_t st_base, uint32_t aByte,
                                              uint32_t bByte, float (&acc)[4][4][4]) {
#pragma unroll
    for (int ks = 0; ks < 2; ks++) {
        uint32_t ah[4][4], al[4][4], bh[2][4], bl[2][4];
#pragma unroll
        for (int np = 0; np < 2; np++) {
            uint32_t bo = st_base + bByte + np * 16 * RB + ks * 32;
            LDSM_X4(bh[np][0], bh[np][1], bh[np][2], bh[np][3], bo + 2 * TILE_BYTES);
            LDSM_X4(bl[np][0], bl[np][1], bl[np][2], bl[np][3], bo + 3 * TILE_BYTES);
        }
#pragma unroll
        for (int mt = 0; mt < 4; mt++) {
            uint32_t ao = st_base + aByte + mt * 16 * RB + ks * 32;
            LDSM_X4(ah[mt][0], ah[mt][1], ah[mt][2], ah[mt][3], ao + 0 * TILE_BYTES);
            LDSM_X4(al[mt][0], al[mt][1], al[mt][2], al[mt][3], ao + 1 * TILE_BYTES);
        }
#pragma unroll
        for (int mt = 0; mt < 4; mt++)
#pragma unroll
            for (int nt = 0; nt < 4; nt++) {
                const uint32_t b0h = bh[nt >> 1][(nt & 1) * 2];
                const uint32_t b1h = bh[nt >> 1][(nt & 1) * 2 + 1];
                const uint32_t b0l = bl[nt >> 1][(nt & 1) * 2];
                const uint32_t b1l = bl[nt >> 1][(nt & 1) * 2 + 1];
                mma16816(acc[mt][nt], ah[mt], b0h, b1h);
                mma16816(acc[mt][nt], ah[mt], b0l, b1l);
                mma16816(acc[mt][nt], al[mt], b0h, b1h);
            }
    }
}

// ---------------------------------------------------------------------------
// Full mainloop: D(128x128 f32, in registers) = AhBh + AhBl + AlBh over Kdim
// 3-stage pipeline, prefetch distance 2, ONE __syncthreads per chunk.
// Invariant at top of iter c: the last committed cp.async group is #(c+1);
// wait_group(1) => group #c (chunk c's tiles) complete. The barrier also
// proves every warp finished compute(c-1), so re-filling stage (c-1)%3 with
// chunk c+2 right after it is safe.
// ---------------------------------------------------------------------------
__device__ __forceinline__ void gemm_core(const __nv_bfloat16* Ah, const __nv_bfloat16* Al,
                                          size_t lda,
                                          const __nv_bfloat16* Bh, const __nv_bfloat16* Bl,
                                          size_t ldb, int Kdim, uint32_t sbase, int tid,
                                          float (&acc)[4][4][4]) {
    const int lane = tid & 31, wid = tid >> 5;
    const int wr = wid >> 2, wc = wid & 3;
    // ldmatrix per-lane base offsets (A: m = lane%16, kblk = lane/16;
    //                                 B: n = lane%8 + 8*((lane/16)&1), kblk = (lane/8)&1)
    const uint32_t aByte = sbase + (uint32_t)((wr * 64 + (lane & 15)) * RB + (lane >> 4) * 16);
    const uint32_t bByte = sbase + (uint32_t)((wc * 32 + (lane & 7) + ((lane >> 4) & 1) * 8) * RB
                                              + ((lane >> 3) & 1) * 16);

    const int nch = Kdim / 32;
    // prologue: chunks 0 and 1 into stages 0 and 1 (groups #0, #1)
    stage_all(Ah, Al, lda, Bh, Bl, ldb, 0,  sbase + 0 * STAGE_BYTES, tid);
    stage_all(Ah, Al, lda, Bh, Bl, ldb, 32, sbase + 1 * STAGE_BYTES, tid);

    int ld_stage = 2;   // stage receiving chunk c+2
    int cm_stage = 0;   // stage holding chunk c
#pragma unroll 1
    for (int c = 0; c < nch; c++) {
        CP_WAIT(1);
        __syncthreads();
        if (c + 2 < nch) {
            stage_all(Ah, Al, lda, Bh, Bl, ldb, (c + 2) * 32,
                      sbase + (uint32_t)(ld_stage * STAGE_BYTES), tid);
        } else {
            CP_COMMIT();   // empty group keeps wait_group arithmetic exact
        }
        ld_stage = (ld_stage == NSTAGE - 1) ? 0 : ld_stage + 1;
        compute_stage((uint32_t)(cm_stage * STAGE_BYTES), aByte, bByte, acc);
        cm_stage = (cm_stage == NSTAGE - 1) ? 0 : cm_stage + 1;
    }
    CP_WAIT(0);
    __syncthreads();
}

// Scatter warp accumulators into a 128x128 f32 smem tile (stride SF)
__device__ __forceinline__ void acc_to_smem(float (&acc)[4][4][4], float* smf, int tid) {
    const int lane = tid & 31, wid = tid >> 5;
    const int wr = wid >> 2, wc = wid & 3;
    const int g = lane >> 2, t = lane & 3;
#pragma unroll
    for (int mt = 0; mt < 4; mt++)
#pragma unroll
        for (int nt = 0; nt < 4; nt++) {
            const int m = wr * 64 + mt * 16 + g;
            const int n = wc * 32 + nt * 8 + 2 * t;
            *reinterpret_cast<float2*>(&smf[m * SF + n]) =
                make_float2(acc[mt][nt][0], acc[mt][nt][1]);
            *reinterpret_cast<float2*>(&smf[(m + 8) * SF + n]) =
                make_float2(acc[mt][nt][2], acc[mt][nt][3]);
        }
}

// ---------------------------------------------------------------------------
// Kernel: fp32 -> (hi, lo) bf16 split
// ---------------------------------------------------------------------------
__global__ void split_kernel(const float* __restrict__ src,
                             __nv_bfloat16* __restrict__ dh,
                             __nv_bfloat16* __restrict__ dl, int n4) {
    int i = blockIdx.x * blockDim.x + threadIdx.x;
    if (i >= n4) return;
    float4 v = reinterpret_cast<const float4*>(src)[i];
    float vv[4] = {v.x, v.y, v.z, v.w};
    __nv_bfloat16 hh[4], ll[4];
#pragma unroll
    for (int j = 0; j < 4; j++) {
        hh[j] = __float2bfloat16(vv[j]);
        ll[j] = __float2bfloat16(vv[j] - __bfloat162float(hh[j]));
    }
    reinterpret_cast<__nv_bfloat162*>(dh)[2 * i]     = __halves2bfloat162(hh[0], hh[1]);
    reinterpret_cast<__nv_bfloat162*>(dh)[2 * i + 1] = __halves2bfloat162(hh[2], hh[3]);
    reinterpret_cast<__nv_bfloat162*>(dl)[2 * i]     = __halves2bfloat162(ll[0], ll[1]);
    reinterpret_cast<__nv_bfloat162*>(dl)[2 * i + 1] = __halves2bfloat162(ll[2], ll[3]);
}

// ---------------------------------------------------------------------------
// Kernel 1: QKV projection.  z=0 -> Q (split), z=1 -> K (split), z=2 -> V^T
// grid = (H/128, M_ALL/128, 3), block = 256
// ---------------------------------------------------------------------------
__global__ void __launch_bounds__(256, 1)
qkv_kernel(const float* __restrict__ bq, const float* __restrict__ bk,
           const float* __restrict__ bv) {
    extern __shared__ char sm[];
    const uint32_t sbase = smem_to_u32(sm);
    const int tid = threadIdx.x;
    const int z = blockIdx.z;
    const int m0 = blockIdx.y * 128, n0 = blockIdx.x * 128;

    const __nv_bfloat16* Ah = g_Xh + (size_t)m0 * H;
    const __nv_bfloat16* Al = g_Xl + (size_t)m0 * H;
    const __nv_bfloat16* Bh = g_Wh + (size_t)z * H * H + (size_t)n0 * H;
    const __nv_bfloat16* Bl = g_Wl + (size_t)z * H * H + (size_t)n0 * H;
    const float* bias = (z == 0) ? bq : (z == 1) ? bk : bv;

    float acc[4][4][4] = {};
    gemm_core(Ah, Al, H, Bh, Bl, H, H, sbase, tid, acc);

    float* smf = reinterpret_cast<float*>(sm);
    acc_to_smem(acc, smf, tid);
    __syncthreads();

    if (z < 2) {
        __nv_bfloat16* outH = (z == 0) ? g_Qh : g_Kh;
        __nv_bfloat16* outL = (z == 0) ? g_Ql : g_Kl;
        const int row = tid >> 1, ch = (tid & 1) * 64;
        const size_t go = (size_t)(m0 + row) * H + n0 + ch;
#pragma unroll
        for (int q = 0; q < 8; q++) {
            uint32_t ph[4], pl[4];
#pragma unroll
            for (int j = 0; j < 4; j++) {
                const int n = ch + q * 8 + 2 * j;
                float c0 = smf[row * SF + n]     + bias[n0 + n];
                float c1 = smf[row * SF + n + 1] + bias[n0 + n + 1];
                __nv_bfloat16 h0 = __float2bfloat16(c0), h1 = __float2bfloat16(c1);
                __nv_bfloat16 l0 = __float2bfloat16(c0 - __bfloat162float(h0));
                __nv_bfloat16 l1 = __float2bfloat16(c1 - __bfloat162float(h1));
                __nv_bfloat162 vh = __halves2bfloat162(h0, h1);
                __nv_bfloat162 vl = __halves2bfloat162(l0, l1);
                ph[j] = *reinterpret_cast<uint32_t*>(&vh);
                pl[j] = *reinterpret_cast<uint32_t*>(&vl);
            }
            *reinterpret_cast<uint4*>(outH + go + q * 8) = *reinterpret_cast<const uint4*>(ph);
            *reinterpret_cast<uint4*>(outL + go + q * 8) = *reinterpret_cast<const uint4*>(pl);
        }
    } else {
        // V transposed: Vt[b][n][s]; threads map to s -> coalesced stores
        const int b = m0 >> 11;
        const int s0 = m0 & 2047;
        const int sl = tid & 127, nh = (tid >> 7) * 64;
#pragma unroll 1
        for (int j = 0; j < 64; j++) {
            const int nl = nh + j;
            float c = smf[sl * SF + nl] + bias[n0 + nl];
            __nv_bfloat16 hv = __float2bfloat16(c);
            __nv_bfloat16 lv = __float2bfloat16(c - __bfloat162float(hv));
            const size_t a = (size_t)b * H * SEQ + (size_t)(n0 + nl) * SEQ + s0 + sl;
            g_Vth[a] = hv;
            g_Vtl[a] = lv;
        }
    }
}

// ---------------------------------------------------------------------------
// Kernel 2: scores S = mask ? (Q.K^T)/32 : -inf.  grid = (16, 16, 4), block 256
// ---------------------------------------------------------------------------
__global__ void __launch_bounds__(256, 1)
scores_kernel(const int* __restrict__ mask) {
    extern __shared__ char sm[];
    const uint32_t sbase = smem_to_u32(sm);
    const int tid = threadIdx.x;
    const int b = blockIdx.z;
    const int m0 = blockIdx.y * 128, n0 = blockIdx.x * 128;

    const size_t rowA = (size_t)(b * SEQ + m0) * H;
    const size_t rowB = (size_t)(b * SEQ + n0) * H;

    float acc[4][4][4] = {};
    gemm_core(g_Qh + rowA, g_Ql + rowA, H, g_Kh + rowB, g_Kl + rowB, H, H,
              sbase, tid, acc);

    float* smf = reinterpret_cast<float*>(sm);
    acc_to_smem(acc, smf, tid);
    __syncthreads();

    const float scale = 0.03125f;  // 1/sqrt(1024)
    const int ql = tid >> 1, ch = (tid & 1) * 64;
    const size_t base = ((size_t)(b * SEQ + m0 + ql)) * SEQ + n0 + ch;
    const int4* mk4 = reinterpret_cast<const int4*>(mask + base);
    float4* dst = reinterpret_cast<float4*>(g_S + base);
#pragma unroll
    for (int j4 = 0; j4 < 16; j4++) {
        float4 v = *reinterpret_cast<const float4*>(&smf[ql * SF + ch + j4 * 4]);
        int4 mk = mk4[j4];
        v.x = mk.x ? v.x * scale : -INFINITY;
        v.y = mk.y ? v.y * scale : -INFINITY;
        v.z = mk.z ? v.z * scale : -INFINITY;
        v.w = mk.w ? v.w * scale : -INFINITY;
        dst[j4] = v;
    }
}

// ---------------------------------------------------------------------------
// Kernel 3: row softmax, fp32 in -> split-bf16 P out.  grid = B*S, block 256
// ---------------------------------------------------------------------------
__global__ void softmax_kernel() {
    const size_t row = (size_t)blockIdx.x * SEQ;
    const float* Srow = g_S + row;
    const int tid = threadIdx.x;

    float v[8];
    float m = -INFINITY;
#pragma unroll
    for (int i = 0; i < 8; i++) {
        v[i] = Srow[i * 256 + tid];
        m = fmaxf(m, v[i]);
    }
#pragma unroll
    for (int o = 16; o > 0; o >>= 1) m = fmaxf(m, __shfl_xor_sync(0xffffffffu, m, o));
    __shared__ float smax[8];
    if ((tid & 31) == 0) smax[tid >> 5] = m;
    __syncthreads();
    float mm = smax[0];
#pragma unroll
    for (int i = 1; i < 8; i++) mm = fmaxf(mm, smax[i]);

    float s = 0.f;
#pragma unroll
    for (int i = 0; i < 8; i++) { v[i] = __expf(v[i] - mm); s += v[i]; }
#pragma unroll
    for (int o = 16; o > 0; o >>= 1) s += __shfl_xor_sync(0xffffffffu, s, o);
    __shared__ float ssum[8];
    if ((tid & 31) == 0) ssum[tid >> 5] = s;
    __syncthreads();
    float tot = 0.f;
#pragma unroll
    for (int i = 0; i < 8; i++) tot += ssum[i];
    const float inv = 1.0f / tot;
#pragma unroll
    for (int i = 0; i < 8; i++) {
        float p = v[i] * inv;
        __nv_bfloat16 h = __float2bfloat16(p);
        __nv_bfloat16 l = __float2bfloat16(p - __bfloat162float(h));
        g_Ph[row + i * 256 + tid] = h;
        g_Pl[row + i * 256 + tid] = l;
    }
}

// ---------------------------------------------------------------------------
// Kernel 4: out = P @ V (NT vs V^T).  grid = (H/128, SEQ/128, 4), block 256
// ---------------------------------------------------------------------------
__global__ void __launch_bounds__(256, 1)
pv_kernel(float* __restrict__ out) {
    extern __shared__ char sm[];
    const uint32_t sbase = smem_to_u32(sm);
    const int tid = threadIdx.x;
    const int b = blockIdx.z;
    const int m0 = blockIdx.y * 128, n0 = blockIdx.x * 128;

    const size_t rowA = ((size_t)b * SEQ + m0) * SEQ;
    const size_t rowB = (size_t)b * H * SEQ + (size_t)n0 * SEQ;

    float acc[4][4][4] = {};
    gemm_core(g_Ph + rowA, g_Pl + rowA, SEQ, g_Vth + rowB, g_Vtl + rowB, SEQ, SEQ,
              sbase, tid, acc);

    float* smf = reinterpret_cast<float*>(sm);
    acc_to_smem(acc, smf, tid);
    __syncthreads();

    const int row = tid >> 1, ch = (tid & 1) * 64;
    const size_t base = ((size_t)(b * SEQ + m0 + row)) * H + n0 + ch;
    float4* dst = reinterpret_cast<float4*>(out + base);
#pragma unroll
    for (int j4 = 0; j4 < 16; j4++)
        dst[j4] = *reinterpret_cast<const float4*>(&smf[row * SF + ch + j4 * 4]);
}

// ---------------------------------------------------------------------------
extern "C" void kernel_launch(void* const* d_in, const int* in_sizes, int n_in,
                              void* d_out, int out_size) {
    const float* x   = (const float*)d_in[0];
    const int*  mask = (const int*)  d_in[1];
    const float* Wq  = (const float*)d_in[2];
    const float* bq  = (const float*)d_in[3];
    const float* Wk  = (const float*)d_in[4];
    const float* bk  = (const float*)d_in[5];
    const float* Wv  = (const float*)d_in[6];
    const float* bv  = (const float*)d_in[7];
    float* out = (float*)d_out;

    cudaFuncSetAttribute(qkv_kernel,    cudaFuncAttributeMaxDynamicSharedMemorySize, SMEM_BYTES);
    cudaFuncSetAttribute(scores_kernel, cudaFuncAttributeMaxDynamicSharedMemorySize, SMEM_BYTES);
    cudaFuncSetAttribute(pv_kernel,     cudaFuncAttributeMaxDynamicSharedMemorySize, SMEM_BYTES);

    __nv_bfloat16 *Xh, *Xl, *Wh, *Wl;
    cudaGetSymbolAddress((void**)&Xh, g_Xh);
    cudaGetSymbolAddress((void**)&Xl, g_Xl);
    cudaGetSymbolAddress((void**)&Wh, g_Wh);
    cudaGetSymbolAddress((void**)&Wl, g_Wl);

    const int n4x = M_ALL * H / 4;
    const int n4w = H * H / 4;
    split_kernel<<<n4x / 256, 256>>>(x, Xh, Xl, n4x);
    split_kernel<<<n4w / 256, 256>>>(Wq, Wh + 0 * (size_t)H * H, Wl + 0 * (size_t)H * H, n4w);
    split_kernel<<<n4w / 256, 256>>>(Wk, Wh + 1 * (size_t)H * H, Wl + 1 * (size_t)H * H, n4w);
    split_kernel<<<n4w / 256, 256>>>(Wv, Wh + 2 * (size_t)H * H, Wl + 2 * (size_t)H * H, n4w);

    qkv_kernel   <<<dim3(H / 128, M_ALL / 128, 3), 256, SMEM_BYTES>>>(bq, bk, bv);
    scores_kernel<<<dim3(SEQ / 128, SEQ / 128, BATCH), 256, SMEM_BYTES>>>(mask);
    softmax_kernel<<<BATCH * SEQ, 256>>>();
    pv_kernel    <<<dim3(H / 128, SEQ / 128, BATCH), 256, SMEM_BYTES>>>(out);
}